// round 1
// baseline (speedup 1.0000x reference)
#include <cuda_runtime.h>
#include <math.h>

#define NN 16384
#define CC 256
#define HH 8
#define DD 64
#define KK 8
#define HD 512
#define HIDD 512
#define OUTD 64
#define NEE 64
#define H2D 532
#define ATTW 520

// ---------------- scratch (static device arrays; no allocation) ----------------
__device__ float g_Q[NN * HD];
__device__ float g_Kx[NN * HD];
__device__ float g_Vx[NN * HD];
__device__ float g_G[NN * HH];
__device__ float g_Att[NN * ATTW];
__device__ float g_T[NN * CC];
__device__ float g_H2[NN * H2D];
__device__ float g_Z[NN * OUTD];
__device__ double g_loss;

__device__ __forceinline__ float gelu_tanh(float x) {
    float x3 = x * x * x;
    return 0.5f * x * (1.0f + tanhf(0.7978845608028654f * (x + 0.044715f * x3)));
}

// ---------------- generic tiled SGEMM, 64x64 block, 4x4 microtile ----------------
// EPI: 0 = plain, 1 = resid + dyntanh, 2 = gelu(bias) + dyntanh, 3 = tanh(gelu(bias))
template <int EPI>
__global__ void gemm64(const float* __restrict__ A, const float* __restrict__ B,
                       float* __restrict__ C, int M, int N, int K, int ldc,
                       const float* __restrict__ bias,
                       const float* __restrict__ resid, int ldr,
                       const float* __restrict__ alpha_p,
                       const float* __restrict__ gv, const float* __restrict__ bv) {
    __shared__ float As[16][64];
    __shared__ float Bs[16][65];
    int tid = threadIdx.x;
    int bm = blockIdx.y * 64, bn = blockIdx.x * 64;
    int ty = tid >> 4, tx = tid & 15;
    float acc[4][4] = {};
    int ar = tid >> 2, akb = (tid & 3) * 4;
    int brw = tid >> 4, bcb = (tid & 15) * 4;

    for (int k0 = 0; k0 < K; k0 += 16) {
#pragma unroll
        for (int i = 0; i < 4; i++) {
            int kk = k0 + akb + i;
            As[akb + i][ar] = (kk < K) ? A[(size_t)(bm + ar) * K + kk] : 0.f;
        }
        {
            int kk = k0 + brw;
#pragma unroll
            for (int i = 0; i < 4; i++) {
                Bs[brw][bcb + i] = (kk < K) ? B[(size_t)kk * N + bn + bcb + i] : 0.f;
            }
        }
        __syncthreads();
#pragma unroll
        for (int k = 0; k < 16; k++) {
            float a[4], b[4];
#pragma unroll
            for (int i = 0; i < 4; i++) a[i] = As[k][ty * 4 + i];
#pragma unroll
            for (int j = 0; j < 4; j++) b[j] = Bs[k][tx * 4 + j];
#pragma unroll
            for (int i = 0; i < 4; i++)
#pragma unroll
                for (int j = 0; j < 4; j++) acc[i][j] = fmaf(a[i], b[j], acc[i][j]);
        }
        __syncthreads();
    }

    float alpha = 0.f;
    if (EPI == 1 || EPI == 2) alpha = *alpha_p;

#pragma unroll
    for (int i = 0; i < 4; i++) {
#pragma unroll
        for (int j = 0; j < 4; j++) {
            int m = bm + ty * 4 + i, n = bn + tx * 4 + j;
            float v = acc[i][j];
            if (EPI == 1) {
                v += resid[(size_t)m * ldr + n];
                v = tanhf(alpha * v) * gv[n] + bv[n];
            } else if (EPI == 2) {
                v = gelu_tanh(v + bias[n]);
                v = tanhf(alpha * v) * gv[n] + bv[n];
            } else if (EPI == 3) {
                v = tanhf(gelu_tanh(v + bias[n]));
            }
            C[(size_t)m * ldc + n] = v;
        }
    }
}

// ---------------- gate projection: G[n,h] = x[n,:] . w_gate[:,h] ----------------
__global__ void gate_kernel(const float* __restrict__ x, const float* __restrict__ wg) {
    int t = blockIdx.x * blockDim.x + threadIdx.x;
    if (t >= NN * HH) return;
    int n = t >> 3, h = t & 7;
    const float* xr = x + (size_t)n * CC;
    float acc = 0.f;
#pragma unroll 4
    for (int c = 0; c < CC; c++) acc = fmaf(xr[c], wg[c * HH + h], acc);
    g_G[t] = acc;
}

// ---------------- attention: block per node, warp per head ----------------
__global__ void attn_kernel(const float* __restrict__ coors, const int* __restrict__ nbr,
                            const float* __restrict__ Wr1, const float* __restrict__ br1,
                            const float* __restrict__ Wr2, const float* __restrict__ br2) {
    int n = blockIdx.x;
    int tid = threadIdx.x;
    __shared__ int s_nbr[8];
    __shared__ float s_dist[8];
    __shared__ float s_unit[8][3];
    __shared__ float s_rad[8][8];
    __shared__ float s_gate[8][8];

    if (tid < 8) s_nbr[tid] = nbr[(size_t)n * 8 + tid];
    __syncthreads();
    if (tid < 8) {
        int j = tid;
        float cx = coors[(size_t)n * 3], cy = coors[(size_t)n * 3 + 1], cz = coors[(size_t)n * 3 + 2];
        int m = s_nbr[j];
        float rx = coors[(size_t)m * 3] - cx;
        float ry = coors[(size_t)m * 3 + 1] - cy;
        float rz = coors[(size_t)m * 3 + 2] - cz;
        float d = sqrtf(rx * rx + ry * ry + rz * rz + 1e-8f);
        s_dist[j] = d;
        s_unit[j][0] = rx / d;
        s_unit[j][1] = ry / d;
        s_unit[j][2] = rz / d;
    }
    __syncthreads();
    if (tid < 64) {
        int j = tid >> 3, h = tid & 7;
        float d = s_dist[j];
        float acc = br2[h];
#pragma unroll
        for (int i = 0; i < 16; i++) acc = fmaf(gelu_tanh(d * Wr1[i] + br1[i]), Wr2[i * 8 + h], acc);
        s_rad[j][h] = acc;
        s_gate[j][h] = g_G[(size_t)s_nbr[j] * HH + h];
    }
    __syncthreads();

    int w = tid >> 5, lane = tid & 31;
    int h = w;
    const float* qr = g_Q + (size_t)n * HD + h * 64;
    float q0 = qr[lane * 2], q1 = qr[lane * 2 + 1];
    float logit[8];
#pragma unroll
    for (int j = 0; j < 8; j++) {
        const float* kr = g_Kx + (size_t)s_nbr[j] * HD + h * 64;
        float p = q0 * kr[lane * 2] + q1 * kr[lane * 2 + 1];
#pragma unroll
        for (int o = 16; o; o >>= 1) p += __shfl_xor_sync(0xffffffffu, p, o);
        p = p * 0.125f + s_rad[j][h];
        logit[j] = (s_dist[j] <= 10.0f) ? p : -1e9f;
    }
    float mx = logit[0];
#pragma unroll
    for (int j = 1; j < 8; j++) mx = fmaxf(mx, logit[j]);
    float e[8];
    float se = 0.f;
#pragma unroll
    for (int j = 0; j < 8; j++) {
        e[j] = expf(logit[j] - mx);
        se += e[j];
    }
    float inv = 1.f / se;
    float a0 = 0.f, a1 = 0.f;
#pragma unroll
    for (int j = 0; j < 8; j++) {
        float at = e[j] * inv;
        const float* vr = g_Vx + (size_t)s_nbr[j] * HD + h * 64;
        a0 = fmaf(at, vr[lane * 2], a0);
        a1 = fmaf(at, vr[lane * 2 + 1], a1);
    }
    g_Att[(size_t)n * ATTW + h * 64 + lane * 2] = a0;
    g_Att[(size_t)n * ATTW + h * 64 + lane * 2 + 1] = a1;
    if (lane == 0) {
        float vx = 0.f, vy = 0.f, vz = 0.f;
#pragma unroll
        for (int j = 0; j < 8; j++) {
            float wg = e[j] * inv * s_gate[j][h];
            vx = fmaf(wg, s_unit[j][0], vx);
            vy = fmaf(wg, s_unit[j][1], vy);
            vz = fmaf(wg, s_unit[j][2], vz);
        }
        g_Att[(size_t)n * ATTW + 512 + h] = sqrtf(vx * vx + vy * vy + vz * vz + 1e-8f);
    }
}

// ---------------- H2 extra columns: aa feats through dyntanh2 ----------------
__global__ void h2extra_kernel(const float* __restrict__ x, const float* __restrict__ alpha2,
                               const float* __restrict__ g2, const float* __restrict__ b2) {
    int t = blockIdx.x * blockDim.x + threadIdx.x;
    if (t >= NN * 20) return;
    int n = t / 20, j = t % 20;
    float a = *alpha2;
    g_H2[(size_t)n * H2D + 512 + j] = tanhf(a * x[(size_t)n * CC + j]) * g2[512 + j] + b2[512 + j];
}

// ---------------- VQ: argmin + quantize + commitment loss ----------------
__global__ void zero_loss_kernel() { g_loss = 0.0; }

__global__ void vq_kernel(const float* __restrict__ cb, float* __restrict__ out) {
    int n = blockIdx.x;
    int t = threadIdx.x;  // 64
    __shared__ float s_z[64];
    __shared__ float s_sc[64];
    __shared__ int s_best;
    s_z[t] = g_Z[(size_t)n * 64 + t];
    __syncthreads();
    float dot = 0.f, cn = 0.f;
    const float* ce = cb + (size_t)t * 64;
#pragma unroll 8
    for (int d = 0; d < 64; d++) {
        float c = ce[d];
        dot = fmaf(s_z[d], c, dot);
        cn = fmaf(c, c, cn);
    }
    s_sc[t] = cn - 2.f * dot;
    __syncthreads();
    if (t == 0) {
        float best = s_sc[0];
        int bi = 0;
        for (int e2 = 1; e2 < 64; e2++)
            if (s_sc[e2] < best) { best = s_sc[e2]; bi = e2; }
        s_best = bi;
    }
    __syncthreads();
    float zq = cb[(size_t)s_best * 64 + t];
    out[(size_t)n * 64 + t] = zq;
    float df = s_z[t] - zq;
    df = df * df;
#pragma unroll
    for (int o = 16; o; o >>= 1) df += __shfl_xor_sync(0xffffffffu, df, o);
    __shared__ float s_part[2];
    if ((t & 31) == 0) s_part[t >> 5] = df;
    __syncthreads();
    if (t == 0) atomicAdd(&g_loss, (double)(s_part[0] + s_part[1]));
}

__global__ void fin_loss_kernel(float* __restrict__ out) {
    out[(size_t)NN * OUTD] = (float)(0.25 * g_loss / (double)((size_t)NN * OUTD));
}

// ---------------- launch ----------------
extern "C" void kernel_launch(void* const* d_in, const int* in_sizes, int n_in,
                              void* d_out, int out_size) {
    const float *x, *coors, *Wq, *Wk, *Wv, *wg, *Wr1, *br1, *Wr2, *br2, *Wo;
    const float *a1, *g1, *b1, *Wlin, *blin, *a2, *g2, *b2, *Wout, *bout, *cb;
    const int* nbr;

    if (n_in > 5 && in_sizes[5] == 2048) {
        // reference-signature order (nbr_idx last)
        x = (const float*)d_in[0];   coors = (const float*)d_in[1];
        Wq = (const float*)d_in[2];  Wk = (const float*)d_in[3];  Wv = (const float*)d_in[4];
        wg = (const float*)d_in[5];  Wr1 = (const float*)d_in[6]; br1 = (const float*)d_in[7];
        Wr2 = (const float*)d_in[8]; br2 = (const float*)d_in[9]; Wo = (const float*)d_in[10];
        a1 = (const float*)d_in[11]; g1 = (const float*)d_in[12]; b1 = (const float*)d_in[13];
        Wlin = (const float*)d_in[14]; blin = (const float*)d_in[15];
        a2 = (const float*)d_in[16]; g2 = (const float*)d_in[17]; b2 = (const float*)d_in[18];
        Wout = (const float*)d_in[19]; bout = (const float*)d_in[20];
        cb = (const float*)d_in[21]; nbr = (const int*)d_in[22];
    } else {
        // setup_inputs dict order
        x = (const float*)d_in[0];   coors = (const float*)d_in[1];
        nbr = (const int*)d_in[2];
        Wq = (const float*)d_in[3];  Wk = (const float*)d_in[4];  Wv = (const float*)d_in[5];
        wg = (const float*)d_in[6];  Wr1 = (const float*)d_in[7]; br1 = (const float*)d_in[8];
        Wr2 = (const float*)d_in[9]; br2 = (const float*)d_in[10]; Wo = (const float*)d_in[11];
        a1 = (const float*)d_in[12]; g1 = (const float*)d_in[13]; b1 = (const float*)d_in[14];
        Wlin = (const float*)d_in[15]; blin = (const float*)d_in[16];
        a2 = (const float*)d_in[17]; g2 = (const float*)d_in[18]; b2 = (const float*)d_in[19];
        Wout = (const float*)d_in[20]; bout = (const float*)d_in[21];
        cb = (const float*)d_in[22];
    }

    float *pQ, *pK, *pV, *pAtt, *pT, *pH2, *pZ;
    cudaGetSymbolAddress((void**)&pQ, g_Q);
    cudaGetSymbolAddress((void**)&pK, g_Kx);
    cudaGetSymbolAddress((void**)&pV, g_Vx);
    cudaGetSymbolAddress((void**)&pAtt, g_Att);
    cudaGetSymbolAddress((void**)&pT, g_T);
    cudaGetSymbolAddress((void**)&pH2, g_H2);
    cudaGetSymbolAddress((void**)&pZ, g_Z);

    float* out = (float*)d_out;

    zero_loss_kernel<<<1, 1>>>();

    // Q/K/V projections (project first, gather later)
    gemm64<0><<<dim3(HD / 64, NN / 64), 256>>>(x, Wq, pQ, NN, HD, CC, HD,
                                               nullptr, nullptr, 0, nullptr, nullptr, nullptr);
    gemm64<0><<<dim3(HD / 64, NN / 64), 256>>>(x, Wk, pK, NN, HD, CC, HD,
                                               nullptr, nullptr, 0, nullptr, nullptr, nullptr);
    gemm64<0><<<dim3(HD / 64, NN / 64), 256>>>(x, Wv, pV, NN, HD, CC, HD,
                                               nullptr, nullptr, 0, nullptr, nullptr, nullptr);
    gate_kernel<<<(NN * HH + 255) / 256, 256>>>(x, wg);

    attn_kernel<<<NN, 256>>>(coors, nbr, Wr1, br1, Wr2, br2);

    // se3_out = x + Att@Wo, fused DynTanh -> T
    gemm64<1><<<dim3(CC / 64, NN / 64), 256>>>(pAtt, Wo, pT, NN, CC, ATTW, CC,
                                               nullptr, x, CC, a1, g1, b1);
    // H2[:, :512] = dyntanh2(gelu(T@Wlin + blin))
    gemm64<2><<<dim3(HIDD / 64, NN / 64), 256>>>(pT, Wlin, pH2, NN, HIDD, CC, H2D,
                                                 blin, nullptr, 0, a2, g2, b2);
    h2extra_kernel<<<(NN * 20 + 255) / 256, 256>>>(x, a2, g2, b2);

    // Z = tanh(gelu(H2@Wout + bout))
    gemm64<3><<<dim3(OUTD / 64, NN / 64), 256>>>(pH2, Wout, pZ, NN, OUTD, H2D, OUTD,
                                                 bout, nullptr, 0, nullptr, nullptr, nullptr);

    vq_kernel<<<NN, 64>>>(cb, out);
    if (out_size > NN * OUTD) fin_loss_kernel<<<1, 1>>>(out);
}

// round 2
// speedup vs baseline: 1.1699x; 1.1699x over previous
#include <cuda_runtime.h>
#include <math.h>

#define NN 16384
#define CC 256
#define HH 8
#define DD 64
#define KK 8
#define HD 512
#define HIDD 512
#define OUTD 64
#define NEE 64
#define H2D 532
#define ATTW 520

// ---------------- scratch (static device arrays; no allocation) ----------------
__device__ float g_Q[NN * HD];
__device__ float g_Kx[NN * HD];
__device__ float g_Vx[NN * HD];
__device__ float g_G[NN * HH];
__device__ float g_Att[NN * ATTW];
__device__ float g_T[NN * CC];
__device__ float g_H2[NN * H2D];
__device__ float g_Z[NN * OUTD];
__device__ double g_loss;

__device__ __forceinline__ float gelu_tanh(float x) {
    float x3 = x * x * x;
    return 0.5f * x * (1.0f + tanhf(0.7978845608028654f * (x + 0.044715f * x3)));
}

// ================= 128x128 SGEMM with packed f32x2 FMA (FFMA2) =================
// EPI: 0 = plain, 1 = resid + dyntanh, 2 = gelu(bias) + dyntanh, 3 = tanh(gelu(bias))
template <int EPI>
__global__ __launch_bounds__(256) void gemm128(
        const float* __restrict__ A, const float* __restrict__ B,
        float* __restrict__ C, int M, int N, int K, int ldc,
        const float* __restrict__ bias,
        const float* __restrict__ resid, int ldr,
        const float* __restrict__ alpha_p,
        const float* __restrict__ gv, const float* __restrict__ bv) {
    __shared__ float As[16][132];   // [k][m], padded stride
    __shared__ float Bs[16][128];   // [k][n]

    int tid = threadIdx.x;
    int bm = blockIdx.y * 128, bn = blockIdx.x * 128;
    int ty = tid >> 4, tx = tid & 15;

    // accumulators: 8 rows x 4 column-pairs, packed (lo=col 2j, hi=col 2j+1)
    unsigned long long acc[8][4];
#pragma unroll
    for (int i = 0; i < 8; i++)
#pragma unroll
        for (int j = 0; j < 4; j++) acc[i][j] = 0ULL;

    // load mappings (2 float4 per thread per tile)
    // A: idx = tid*2+q -> row = idx>>2, kq = (idx&3)*4   (K must be %4==0)
    // B: idx = tid*2+q -> kr = idx>>5, col = (idx&31)*4
    float4 pa[2], pb[2];
    const float4 z4 = make_float4(0.f, 0.f, 0.f, 0.f);

    int nchunk = (K + 15) >> 4;

    // prefetch chunk 0
#pragma unroll
    for (int q = 0; q < 2; q++) {
        int idx = tid * 2 + q;
        int row = idx >> 2, kq = (idx & 3) * 4;
        pa[q] = (kq < K) ? *(const float4*)&A[(size_t)(bm + row) * K + kq] : z4;
        int kr = idx >> 5, col = (idx & 31) * 4;
        pb[q] = (kr < K) ? *(const float4*)&B[(size_t)kr * N + bn + col] : z4;
    }

    for (int c = 0; c < nchunk; c++) {
        // store current chunk to smem
#pragma unroll
        for (int q = 0; q < 2; q++) {
            int idx = tid * 2 + q;
            int row = idx >> 2, kq = (idx & 3) * 4;
            As[kq + 0][row] = pa[q].x;
            As[kq + 1][row] = pa[q].y;
            As[kq + 2][row] = pa[q].z;
            As[kq + 3][row] = pa[q].w;
            int kr = idx >> 5, col = (idx & 31) * 4;
            *(float4*)&Bs[kr][col] = pb[q];
        }
        __syncthreads();

        // prefetch next chunk into registers (overlaps with compute)
        int k0n = (c + 1) * 16;
        if (c + 1 < nchunk) {
#pragma unroll
            for (int q = 0; q < 2; q++) {
                int idx = tid * 2 + q;
                int row = idx >> 2, kq = (idx & 3) * 4;
                int kk = k0n + kq;
                pa[q] = (kk < K) ? *(const float4*)&A[(size_t)(bm + row) * K + kk] : z4;
                int kr = idx >> 5, col = (idx & 31) * 4;
                int kb = k0n + kr;
                pb[q] = (kb < K) ? *(const float4*)&B[(size_t)kb * N + bn + col] : z4;
            }
        }

#pragma unroll
        for (int kk = 0; kk < 16; kk++) {
            float4 af0 = *(const float4*)&As[kk][ty * 8];
            float4 af1 = *(const float4*)&As[kk][ty * 8 + 4];
            ulonglong2 b0 = *(const ulonglong2*)&Bs[kk][tx * 8];
            ulonglong2 b1 = *(const ulonglong2*)&Bs[kk][tx * 8 + 4];
            unsigned long long bp[4] = {b0.x, b0.y, b1.x, b1.y};
            float av[8] = {af0.x, af0.y, af0.z, af0.w, af1.x, af1.y, af1.z, af1.w};
#pragma unroll
            for (int i = 0; i < 8; i++) {
                unsigned long long ap;
                asm("mov.b64 %0, {%1, %1};" : "=l"(ap) : "r"(__float_as_uint(av[i])));
#pragma unroll
                for (int j = 0; j < 4; j++) {
                    asm("fma.rn.f32x2 %0, %1, %2, %0;"
                        : "+l"(acc[i][j]) : "l"(ap), "l"(bp[j]));
                }
            }
        }
        __syncthreads();
    }

    float alpha = 0.f;
    if (EPI == 1 || EPI == 2) alpha = *alpha_p;

#pragma unroll
    for (int i = 0; i < 8; i++) {
        int m = bm + ty * 8 + i;
#pragma unroll
        for (int j = 0; j < 4; j++) {
            unsigned int lo = (unsigned int)(acc[i][j] & 0xffffffffULL);
            unsigned int hi = (unsigned int)(acc[i][j] >> 32);
            float v[2] = {__uint_as_float(lo), __uint_as_float(hi)};
#pragma unroll
            for (int s = 0; s < 2; s++) {
                int n = bn + tx * 8 + j * 2 + s;
                float val = v[s];
                if (EPI == 1) {
                    val += resid[(size_t)m * ldr + n];
                    val = tanhf(alpha * val) * gv[n] + bv[n];
                } else if (EPI == 2) {
                    val = gelu_tanh(val + bias[n]);
                    val = tanhf(alpha * val) * gv[n] + bv[n];
                } else if (EPI == 3) {
                    val = tanhf(gelu_tanh(val + bias[n]));
                }
                C[(size_t)m * ldc + n] = val;
            }
        }
    }
}

// ---------------- legacy 64x64 SGEMM (used for narrow Wout GEMM) ----------------
template <int EPI>
__global__ void gemm64(const float* __restrict__ A, const float* __restrict__ B,
                       float* __restrict__ C, int M, int N, int K, int ldc,
                       const float* __restrict__ bias,
                       const float* __restrict__ resid, int ldr,
                       const float* __restrict__ alpha_p,
                       const float* __restrict__ gv, const float* __restrict__ bv) {
    __shared__ float As[16][64];
    __shared__ float Bs[16][65];
    int tid = threadIdx.x;
    int bm = blockIdx.y * 64, bn = blockIdx.x * 64;
    int ty = tid >> 4, tx = tid & 15;
    float acc[4][4] = {};
    int ar = tid >> 2, akb = (tid & 3) * 4;
    int brw = tid >> 4, bcb = (tid & 15) * 4;

    for (int k0 = 0; k0 < K; k0 += 16) {
#pragma unroll
        for (int i = 0; i < 4; i++) {
            int kk = k0 + akb + i;
            As[akb + i][ar] = (kk < K) ? A[(size_t)(bm + ar) * K + kk] : 0.f;
        }
        {
            int kk = k0 + brw;
#pragma unroll
            for (int i = 0; i < 4; i++) {
                Bs[brw][bcb + i] = (kk < K) ? B[(size_t)kk * N + bn + bcb + i] : 0.f;
            }
        }
        __syncthreads();
#pragma unroll
        for (int k = 0; k < 16; k++) {
            float a[4], b[4];
#pragma unroll
            for (int i = 0; i < 4; i++) a[i] = As[k][ty * 4 + i];
#pragma unroll
            for (int j = 0; j < 4; j++) b[j] = Bs[k][tx * 4 + j];
#pragma unroll
            for (int i = 0; i < 4; i++)
#pragma unroll
                for (int j = 0; j < 4; j++) acc[i][j] = fmaf(a[i], b[j], acc[i][j]);
        }
        __syncthreads();
    }

    float alpha = 0.f;
    if (EPI == 1 || EPI == 2) alpha = *alpha_p;

#pragma unroll
    for (int i = 0; i < 4; i++) {
#pragma unroll
        for (int j = 0; j < 4; j++) {
            int m = bm + ty * 4 + i, n = bn + tx * 4 + j;
            float v = acc[i][j];
            if (EPI == 1) {
                v += resid[(size_t)m * ldr + n];
                v = tanhf(alpha * v) * gv[n] + bv[n];
            } else if (EPI == 2) {
                v = gelu_tanh(v + bias[n]);
                v = tanhf(alpha * v) * gv[n] + bv[n];
            } else if (EPI == 3) {
                v = tanhf(gelu_tanh(v + bias[n]));
            }
            C[(size_t)m * ldc + n] = v;
        }
    }
}

// ---------------- gate projection: G[n,h] = x[n,:] . w_gate[:,h] ----------------
__global__ void gate_kernel(const float* __restrict__ x, const float* __restrict__ wg) {
    int t = blockIdx.x * blockDim.x + threadIdx.x;
    if (t >= NN * HH) return;
    int n = t >> 3, h = t & 7;
    const float* xr = x + (size_t)n * CC;
    float acc = 0.f;
#pragma unroll 4
    for (int c = 0; c < CC; c++) acc = fmaf(xr[c], wg[c * HH + h], acc);
    g_G[t] = acc;
}

// ---------------- attention: block per node, warp per head ----------------
__global__ void attn_kernel(const float* __restrict__ coors, const int* __restrict__ nbr,
                            const float* __restrict__ Wr1, const float* __restrict__ br1,
                            const float* __restrict__ Wr2, const float* __restrict__ br2) {
    int n = blockIdx.x;
    int tid = threadIdx.x;
    __shared__ int s_nbr[8];
    __shared__ float s_dist[8];
    __shared__ float s_unit[8][3];
    __shared__ float s_rad[8][8];
    __shared__ float s_gate[8][8];

    if (tid < 8) s_nbr[tid] = nbr[(size_t)n * 8 + tid];
    __syncthreads();
    if (tid < 8) {
        int j = tid;
        float cx = coors[(size_t)n * 3], cy = coors[(size_t)n * 3 + 1], cz = coors[(size_t)n * 3 + 2];
        int m = s_nbr[j];
        float rx = coors[(size_t)m * 3] - cx;
        float ry = coors[(size_t)m * 3 + 1] - cy;
        float rz = coors[(size_t)m * 3 + 2] - cz;
        float d = sqrtf(rx * rx + ry * ry + rz * rz + 1e-8f);
        s_dist[j] = d;
        s_unit[j][0] = rx / d;
        s_unit[j][1] = ry / d;
        s_unit[j][2] = rz / d;
    }
    __syncthreads();
    if (tid < 64) {
        int j = tid >> 3, h = tid & 7;
        float d = s_dist[j];
        float acc = br2[h];
#pragma unroll
        for (int i = 0; i < 16; i++) acc = fmaf(gelu_tanh(d * Wr1[i] + br1[i]), Wr2[i * 8 + h], acc);
        s_rad[j][h] = acc;
        s_gate[j][h] = g_G[(size_t)s_nbr[j] * HH + h];
    }
    __syncthreads();

    int w = tid >> 5, lane = tid & 31;
    int h = w;
    const float* qr = g_Q + (size_t)n * HD + h * 64;
    float q0 = qr[lane * 2], q1 = qr[lane * 2 + 1];
    float logit[8];
#pragma unroll
    for (int j = 0; j < 8; j++) {
        const float* kr = g_Kx + (size_t)s_nbr[j] * HD + h * 64;
        float p = q0 * kr[lane * 2] + q1 * kr[lane * 2 + 1];
#pragma unroll
        for (int o = 16; o; o >>= 1) p += __shfl_xor_sync(0xffffffffu, p, o);
        p = p * 0.125f + s_rad[j][h];
        logit[j] = (s_dist[j] <= 10.0f) ? p : -1e9f;
    }
    float mx = logit[0];
#pragma unroll
    for (int j = 1; j < 8; j++) mx = fmaxf(mx, logit[j]);
    float e[8];
    float se = 0.f;
#pragma unroll
    for (int j = 0; j < 8; j++) {
        e[j] = expf(logit[j] - mx);
        se += e[j];
    }
    float inv = 1.f / se;
    float a0 = 0.f, a1 = 0.f;
#pragma unroll
    for (int j = 0; j < 8; j++) {
        float at = e[j] * inv;
        const float* vr = g_Vx + (size_t)s_nbr[j] * HD + h * 64;
        a0 = fmaf(at, vr[lane * 2], a0);
        a1 = fmaf(at, vr[lane * 2 + 1], a1);
    }
    g_Att[(size_t)n * ATTW + h * 64 + lane * 2] = a0;
    g_Att[(size_t)n * ATTW + h * 64 + lane * 2 + 1] = a1;
    if (lane == 0) {
        float vx = 0.f, vy = 0.f, vz = 0.f;
#pragma unroll
        for (int j = 0; j < 8; j++) {
            float wg = e[j] * inv * s_gate[j][h];
            vx = fmaf(wg, s_unit[j][0], vx);
            vy = fmaf(wg, s_unit[j][1], vy);
            vz = fmaf(wg, s_unit[j][2], vz);
        }
        g_Att[(size_t)n * ATTW + 512 + h] = sqrtf(vx * vx + vy * vy + vz * vz + 1e-8f);
    }
}

// ---------------- H2 extra columns: aa feats through dyntanh2 ----------------
__global__ void h2extra_kernel(const float* __restrict__ x, const float* __restrict__ alpha2,
                               const float* __restrict__ g2, const float* __restrict__ b2) {
    int t = blockIdx.x * blockDim.x + threadIdx.x;
    if (t >= NN * 20) return;
    int n = t / 20, j = t % 20;
    float a = *alpha2;
    g_H2[(size_t)n * H2D + 512 + j] = tanhf(a * x[(size_t)n * CC + j]) * g2[512 + j] + b2[512 + j];
}

// ---------------- VQ: argmin + quantize + commitment loss ----------------
__global__ void zero_loss_kernel() { g_loss = 0.0; }

__global__ void vq_kernel(const float* __restrict__ cb, float* __restrict__ out) {
    int n = blockIdx.x;
    int t = threadIdx.x;  // 64
    __shared__ float s_z[64];
    __shared__ float s_sc[64];
    __shared__ int s_best;
    s_z[t] = g_Z[(size_t)n * 64 + t];
    __syncthreads();
    float dot = 0.f, cn = 0.f;
    const float* ce = cb + (size_t)t * 64;
#pragma unroll 8
    for (int d = 0; d < 64; d++) {
        float c = ce[d];
        dot = fmaf(s_z[d], c, dot);
        cn = fmaf(c, c, cn);
    }
    s_sc[t] = cn - 2.f * dot;
    __syncthreads();
    if (t == 0) {
        float best = s_sc[0];
        int bi = 0;
        for (int e2 = 1; e2 < 64; e2++)
            if (s_sc[e2] < best) { best = s_sc[e2]; bi = e2; }
        s_best = bi;
    }
    __syncthreads();
    float zq = cb[(size_t)s_best * 64 + t];
    out[(size_t)n * 64 + t] = zq;
    float df = s_z[t] - zq;
    df = df * df;
#pragma unroll
    for (int o = 16; o; o >>= 1) df += __shfl_xor_sync(0xffffffffu, df, o);
    __shared__ float s_part[2];
    if ((t & 31) == 0) s_part[t >> 5] = df;
    __syncthreads();
    if (t == 0) atomicAdd(&g_loss, (double)(s_part[0] + s_part[1]));
}

__global__ void fin_loss_kernel(float* __restrict__ out) {
    out[(size_t)NN * OUTD] = (float)(0.25 * g_loss / (double)((size_t)NN * OUTD));
}

// ---------------- launch ----------------
extern "C" void kernel_launch(void* const* d_in, const int* in_sizes, int n_in,
                              void* d_out, int out_size) {
    const float *x, *coors, *Wq, *Wk, *Wv, *wg, *Wr1, *br1, *Wr2, *br2, *Wo;
    const float *a1, *g1, *b1, *Wlin, *blin, *a2, *g2, *b2, *Wout, *bout, *cb;
    const int* nbr;

    if (n_in > 5 && in_sizes[5] == 2048) {
        // reference-signature order (nbr_idx last)
        x = (const float*)d_in[0];   coors = (const float*)d_in[1];
        Wq = (const float*)d_in[2];  Wk = (const float*)d_in[3];  Wv = (const float*)d_in[4];
        wg = (const float*)d_in[5];  Wr1 = (const float*)d_in[6]; br1 = (const float*)d_in[7];
        Wr2 = (const float*)d_in[8]; br2 = (const float*)d_in[9]; Wo = (const float*)d_in[10];
        a1 = (const float*)d_in[11]; g1 = (const float*)d_in[12]; b1 = (const float*)d_in[13];
        Wlin = (const float*)d_in[14]; blin = (const float*)d_in[15];
        a2 = (const float*)d_in[16]; g2 = (const float*)d_in[17]; b2 = (const float*)d_in[18];
        Wout = (const float*)d_in[19]; bout = (const float*)d_in[20];
        cb = (const float*)d_in[21]; nbr = (const int*)d_in[22];
    } else {
        // setup_inputs dict order
        x = (const float*)d_in[0];   coors = (const float*)d_in[1];
        nbr = (const int*)d_in[2];
        Wq = (const float*)d_in[3];  Wk = (const float*)d_in[4];  Wv = (const float*)d_in[5];
        wg = (const float*)d_in[6];  Wr1 = (const float*)d_in[7]; br1 = (const float*)d_in[8];
        Wr2 = (const float*)d_in[9]; br2 = (const float*)d_in[10]; Wo = (const float*)d_in[11];
        a1 = (const float*)d_in[12]; g1 = (const float*)d_in[13]; b1 = (const float*)d_in[14];
        Wlin = (const float*)d_in[15]; blin = (const float*)d_in[16];
        a2 = (const float*)d_in[17]; g2 = (const float*)d_in[18]; b2 = (const float*)d_in[19];
        Wout = (const float*)d_in[20]; bout = (const float*)d_in[21];
        cb = (const float*)d_in[22];
    }

    float *pQ, *pK, *pV, *pAtt, *pT, *pH2, *pZ;
    cudaGetSymbolAddress((void**)&pQ, g_Q);
    cudaGetSymbolAddress((void**)&pK, g_Kx);
    cudaGetSymbolAddress((void**)&pV, g_Vx);
    cudaGetSymbolAddress((void**)&pAtt, g_Att);
    cudaGetSymbolAddress((void**)&pT, g_T);
    cudaGetSymbolAddress((void**)&pH2, g_H2);
    cudaGetSymbolAddress((void**)&pZ, g_Z);

    float* out = (float*)d_out;

    zero_loss_kernel<<<1, 1>>>();

    // Q/K/V projections (project first, gather later)
    gemm128<0><<<dim3(HD / 128, NN / 128), 256>>>(x, Wq, pQ, NN, HD, CC, HD,
                                                  nullptr, nullptr, 0, nullptr, nullptr, nullptr);
    gemm128<0><<<dim3(HD / 128, NN / 128), 256>>>(x, Wk, pK, NN, HD, CC, HD,
                                                  nullptr, nullptr, 0, nullptr, nullptr, nullptr);
    gemm128<0><<<dim3(HD / 128, NN / 128), 256>>>(x, Wv, pV, NN, HD, CC, HD,
                                                  nullptr, nullptr, 0, nullptr, nullptr, nullptr);
    gate_kernel<<<(NN * HH + 255) / 256, 256>>>(x, wg);

    attn_kernel<<<NN, 256>>>(coors, nbr, Wr1, br1, Wr2, br2);

    // se3_out = x + Att@Wo, fused DynTanh -> T
    gemm128<1><<<dim3(CC / 128, NN / 128), 256>>>(pAtt, Wo, pT, NN, CC, ATTW, CC,
                                                  nullptr, x, CC, a1, g1, b1);
    // H2[:, :512] = dyntanh2(gelu(T@Wlin + blin))
    gemm128<2><<<dim3(HIDD / 128, NN / 128), 256>>>(pT, Wlin, pH2, NN, HIDD, CC, H2D,
                                                    blin, nullptr, 0, a2, g2, b2);
    h2extra_kernel<<<(NN * 20 + 255) / 256, 256>>>(x, a2, g2, b2);

    // Z = tanh(gelu(H2@Wout + bout))
    gemm64<3><<<dim3(OUTD / 64, NN / 64), 256>>>(pH2, Wout, pZ, NN, OUTD, H2D, OUTD,
                                                 bout, nullptr, 0, nullptr, nullptr, nullptr);

    vq_kernel<<<NN, 64>>>(cb, out);
    if (out_size > NN * OUTD) fin_loss_kernel<<<1, 1>>>(out);
}

// round 3
// speedup vs baseline: 1.3340x; 1.1402x over previous
#include <cuda_runtime.h>
#include <math.h>

#define NN 16384
#define CC 256
#define HH 8
#define DD 64
#define KK 8
#define HD 512
#define QKVW 1536
#define HIDD 512
#define OUTD 64
#define NEE 64
#define H2D 532
#define ATTW 520

// ---------------- scratch (static device arrays; no allocation) ----------------
__device__ float g_QKV[NN * QKVW];   // [n][0:512)=Q, [512:1024)=K, [1024:1536)=V
__device__ float g_G[NN * HH];
__device__ float g_Att[NN * ATTW];
__device__ float g_T[NN * CC];
__device__ float g_H2[NN * H2D];
__device__ float g_Z[NN * OUTD];
__device__ double g_loss;

__device__ __forceinline__ float gelu_tanh(float x) {
    float x3 = x * x * x;
    return 0.5f * x * (1.0f + tanhf(0.7978845608028654f * (x + 0.044715f * x3)));
}

// ============== 128x128 SGEMM, FFMA2, pre-duplicated A pairs, 2 CTAs/SM ==========
// EPI: 0 = plain, 1 = resid + dyntanh, 2 = gelu(bias) + dyntanh
// QKV: B selected from {B0,B1,B2} by output-column block (each 512 wide)
template <int EPI, int QKV>
__global__ __launch_bounds__(256, 2) void gemmT(
        const float* __restrict__ A,
        const float* __restrict__ B0, const float* __restrict__ B1,
        const float* __restrict__ B2,
        float* __restrict__ C, int M, int K, int ldb, int ldc,
        const float* __restrict__ bias,
        const float* __restrict__ resid, int ldr,
        const float* __restrict__ alpha_p,
        const float* __restrict__ gv, const float* __restrict__ bv) {
    __shared__ float2 As2[16][128];  // duplicated pairs [k][m]
    __shared__ float Bs[16][128];    // [k][n]

    int tid = threadIdx.x;
    int bm = blockIdx.y * 128;
    int bnc = blockIdx.x * 128;  // output column base
    const float* B = B0;
    int bnb = bnc;  // column base within B
    if (QKV) {
        int sel = bnc >> 9;
        B = (sel == 0) ? B0 : ((sel == 1) ? B1 : B2);
        bnb = bnc & 511;
    }

    int ty = tid >> 4, tx = tid & 15;

    unsigned long long acc[8][4];
#pragma unroll
    for (int i = 0; i < 8; i++)
#pragma unroll
        for (int j = 0; j < 4; j++) acc[i][j] = 0ULL;

    float4 pa[2], pb[2];
    const float4 z4 = make_float4(0.f, 0.f, 0.f, 0.f);
    int nchunk = (K + 15) >> 4;

    // prefetch chunk 0
#pragma unroll
    for (int q = 0; q < 2; q++) {
        int idx = tid * 2 + q;
        int row = idx >> 2, kq = (idx & 3) * 4;
        pa[q] = (kq < K) ? *(const float4*)&A[(size_t)(bm + row) * K + kq] : z4;
        int kr = idx >> 5, col = (idx & 31) * 4;
        pb[q] = (kr < K) ? *(const float4*)&B[(size_t)kr * ldb + bnb + col] : z4;
    }

    for (int c = 0; c < nchunk; c++) {
#pragma unroll
        for (int q = 0; q < 2; q++) {
            int idx = tid * 2 + q;
            int row = idx >> 2, kq = (idx & 3) * 4;
            As2[kq + 0][row] = make_float2(pa[q].x, pa[q].x);
            As2[kq + 1][row] = make_float2(pa[q].y, pa[q].y);
            As2[kq + 2][row] = make_float2(pa[q].z, pa[q].z);
            As2[kq + 3][row] = make_float2(pa[q].w, pa[q].w);
            int kr = idx >> 5, col = (idx & 31) * 4;
            *(float4*)&Bs[kr][col] = pb[q];
        }
        __syncthreads();

        // prefetch next chunk (overlaps compute)
        int k0n = (c + 1) * 16;
        if (c + 1 < nchunk) {
#pragma unroll
            for (int q = 0; q < 2; q++) {
                int idx = tid * 2 + q;
                int row = idx >> 2, kq = (idx & 3) * 4;
                int kk = k0n + kq;
                pa[q] = (kk < K) ? *(const float4*)&A[(size_t)(bm + row) * K + kk] : z4;
                int kr = idx >> 5, col = (idx & 31) * 4;
                int kb = k0n + kr;
                pb[q] = (kb < K) ? *(const float4*)&B[(size_t)kb * ldb + bnb + col] : z4;
            }
        }

#pragma unroll
        for (int kk = 0; kk < 16; kk++) {
            const ulonglong2* ap = (const ulonglong2*)&As2[kk][ty * 8];
            ulonglong2 a01 = ap[0], a23 = ap[1], a45 = ap[2], a67 = ap[3];
            ulonglong2 blo = *(const ulonglong2*)&Bs[kk][tx * 4];
            ulonglong2 bhi = *(const ulonglong2*)&Bs[kk][64 + tx * 4];
            unsigned long long av[8] = {a01.x, a01.y, a23.x, a23.y,
                                        a45.x, a45.y, a67.x, a67.y};
            unsigned long long bp[4] = {blo.x, blo.y, bhi.x, bhi.y};
#pragma unroll
            for (int i = 0; i < 8; i++) {
#pragma unroll
                for (int j = 0; j < 4; j++) {
                    asm("fma.rn.f32x2 %0, %1, %2, %0;"
                        : "+l"(acc[i][j]) : "l"(av[i]), "l"(bp[j]));
                }
            }
        }
        __syncthreads();
    }

    float alpha = 0.f;
    if (EPI == 1 || EPI == 2) alpha = *alpha_p;

#pragma unroll
    for (int i = 0; i < 8; i++) {
        int m = bm + ty * 8 + i;
#pragma unroll
        for (int jj = 0; jj < 4; jj++) {
            unsigned int lo = (unsigned int)(acc[i][jj] & 0xffffffffULL);
            unsigned int hi = (unsigned int)(acc[i][jj] >> 32);
            float v[2] = {__uint_as_float(lo), __uint_as_float(hi)};
#pragma unroll
            for (int s = 0; s < 2; s++) {
                int ncol = bnc + ((jj < 2) ? (tx * 4 + jj * 2 + s)
                                           : (64 + tx * 4 + (jj - 2) * 2 + s));
                float val = v[s];
                if (EPI == 1) {
                    val += resid[(size_t)m * ldr + ncol];
                    val = tanhf(alpha * val) * gv[ncol] + bv[ncol];
                } else if (EPI == 2) {
                    val = gelu_tanh(val + bias[ncol]);
                    val = tanhf(alpha * val) * gv[ncol] + bv[ncol];
                }
                C[(size_t)m * ldc + ncol] = val;
            }
        }
    }
}

// ---------------- legacy 64x64 SGEMM (narrow Wout GEMM, EPI3) ----------------
__global__ void gemm64o(const float* __restrict__ A, const float* __restrict__ B,
                        float* __restrict__ C, int M, int N, int K, int ldc,
                        const float* __restrict__ bias) {
    __shared__ float As[16][64];
    __shared__ float Bs[16][65];
    int tid = threadIdx.x;
    int bm = blockIdx.y * 64, bn = blockIdx.x * 64;
    int ty = tid >> 4, tx = tid & 15;
    float acc[4][4] = {};
    int ar = tid >> 2, akb = (tid & 3) * 4;
    int brw = tid >> 4, bcb = (tid & 15) * 4;

    for (int k0 = 0; k0 < K; k0 += 16) {
#pragma unroll
        for (int i = 0; i < 4; i++) {
            int kk = k0 + akb + i;
            As[akb + i][ar] = (kk < K) ? A[(size_t)(bm + ar) * K + kk] : 0.f;
        }
        {
            int kk = k0 + brw;
#pragma unroll
            for (int i = 0; i < 4; i++) {
                Bs[brw][bcb + i] = (kk < K) ? B[(size_t)kk * N + bn + bcb + i] : 0.f;
            }
        }
        __syncthreads();
#pragma unroll
        for (int k = 0; k < 16; k++) {
            float a[4], b[4];
#pragma unroll
            for (int i = 0; i < 4; i++) a[i] = As[k][ty * 4 + i];
#pragma unroll
            for (int j = 0; j < 4; j++) b[j] = Bs[k][tx * 4 + j];
#pragma unroll
            for (int i = 0; i < 4; i++)
#pragma unroll
                for (int j = 0; j < 4; j++) acc[i][j] = fmaf(a[i], b[j], acc[i][j]);
        }
        __syncthreads();
    }

#pragma unroll
    for (int i = 0; i < 4; i++) {
#pragma unroll
        for (int j = 0; j < 4; j++) {
            int m = bm + ty * 4 + i, n = bn + tx * 4 + j;
            float v = acc[i][j];
            v = tanhf(gelu_tanh(v + bias[n]));
            C[(size_t)m * ldc + n] = v;
        }
    }
}

// ---------------- gate projection: G[n,h] = x[n,:] . w_gate[:,h] ----------------
__global__ void gate_kernel(const float* __restrict__ x, const float* __restrict__ wg) {
    int t = blockIdx.x * blockDim.x + threadIdx.x;
    if (t >= NN * HH) return;
    int n = t >> 3, h = t & 7;
    const float* xr = x + (size_t)n * CC;
    float acc = 0.f;
#pragma unroll 4
    for (int c = 0; c < CC; c++) acc = fmaf(xr[c], wg[c * HH + h], acc);
    g_G[t] = acc;
}

// ---------------- attention: block per node, warp per head ----------------
__global__ void attn_kernel(const float* __restrict__ coors, const int* __restrict__ nbr,
                            const float* __restrict__ Wr1, const float* __restrict__ br1,
                            const float* __restrict__ Wr2, const float* __restrict__ br2) {
    int n = blockIdx.x;
    int tid = threadIdx.x;
    __shared__ int s_nbr[8];
    __shared__ float s_dist[8];
    __shared__ float s_unit[8][3];
    __shared__ float s_rad[8][8];
    __shared__ float s_gate[8][8];

    if (tid < 8) s_nbr[tid] = nbr[(size_t)n * 8 + tid];
    __syncthreads();
    if (tid < 8) {
        int j = tid;
        float cx = coors[(size_t)n * 3], cy = coors[(size_t)n * 3 + 1], cz = coors[(size_t)n * 3 + 2];
        int m = s_nbr[j];
        float rx = coors[(size_t)m * 3] - cx;
        float ry = coors[(size_t)m * 3 + 1] - cy;
        float rz = coors[(size_t)m * 3 + 2] - cz;
        float d = sqrtf(rx * rx + ry * ry + rz * rz + 1e-8f);
        s_dist[j] = d;
        s_unit[j][0] = rx / d;
        s_unit[j][1] = ry / d;
        s_unit[j][2] = rz / d;
    }
    __syncthreads();
    if (tid < 64) {
        int j = tid >> 3, h = tid & 7;
        float d = s_dist[j];
        float acc = br2[h];
#pragma unroll
        for (int i = 0; i < 16; i++) acc = fmaf(gelu_tanh(d * Wr1[i] + br1[i]), Wr2[i * 8 + h], acc);
        s_rad[j][h] = acc;
        s_gate[j][h] = g_G[(size_t)s_nbr[j] * HH + h];
    }
    __syncthreads();

    int w = tid >> 5, lane = tid & 31;
    int h = w;
    const float* qr = g_QKV + (size_t)n * QKVW + h * 64;
    float q0 = qr[lane * 2], q1 = qr[lane * 2 + 1];
    float logit[8];
#pragma unroll
    for (int j = 0; j < 8; j++) {
        const float* kr = g_QKV + (size_t)s_nbr[j] * QKVW + 512 + h * 64;
        float p = q0 * kr[lane * 2] + q1 * kr[lane * 2 + 1];
#pragma unroll
        for (int o = 16; o; o >>= 1) p += __shfl_xor_sync(0xffffffffu, p, o);
        p = p * 0.125f + s_rad[j][h];
        logit[j] = (s_dist[j] <= 10.0f) ? p : -1e9f;
    }
    float mx = logit[0];
#pragma unroll
    for (int j = 1; j < 8; j++) mx = fmaxf(mx, logit[j]);
    float e[8];
    float se = 0.f;
#pragma unroll
    for (int j = 0; j < 8; j++) {
        e[j] = expf(logit[j] - mx);
        se += e[j];
    }
    float inv = 1.f / se;
    float a0 = 0.f, a1 = 0.f;
#pragma unroll
    for (int j = 0; j < 8; j++) {
        float at = e[j] * inv;
        const float* vr = g_QKV + (size_t)s_nbr[j] * QKVW + 1024 + h * 64;
        a0 = fmaf(at, vr[lane * 2], a0);
        a1 = fmaf(at, vr[lane * 2 + 1], a1);
    }
    g_Att[(size_t)n * ATTW + h * 64 + lane * 2] = a0;
    g_Att[(size_t)n * ATTW + h * 64 + lane * 2 + 1] = a1;
    if (lane == 0) {
        float vx = 0.f, vy = 0.f, vz = 0.f;
#pragma unroll
        for (int j = 0; j < 8; j++) {
            float wg = e[j] * inv * s_gate[j][h];
            vx = fmaf(wg, s_unit[j][0], vx);
            vy = fmaf(wg, s_unit[j][1], vy);
            vz = fmaf(wg, s_unit[j][2], vz);
        }
        g_Att[(size_t)n * ATTW + 512 + h] = sqrtf(vx * vx + vy * vy + vz * vz + 1e-8f);
    }
}

// ---------------- H2 extra columns: aa feats through dyntanh2 ----------------
__global__ void h2extra_kernel(const float* __restrict__ x, const float* __restrict__ alpha2,
                               const float* __restrict__ g2, const float* __restrict__ b2) {
    int t = blockIdx.x * blockDim.x + threadIdx.x;
    if (t >= NN * 20) return;
    int n = t / 20, j = t % 20;
    float a = *alpha2;
    g_H2[(size_t)n * H2D + 512 + j] = tanhf(a * x[(size_t)n * CC + j]) * g2[512 + j] + b2[512 + j];
}

// ---------------- VQ: argmin + quantize + commitment loss ----------------
__global__ void zero_loss_kernel() { g_loss = 0.0; }

__global__ void vq_kernel(const float* __restrict__ cb, float* __restrict__ out) {
    int n = blockIdx.x;
    int t = threadIdx.x;  // 64
    __shared__ float s_z[64];
    __shared__ float s_sc[64];
    __shared__ int s_best;
    s_z[t] = g_Z[(size_t)n * 64 + t];
    __syncthreads();
    float dot = 0.f, cn = 0.f;
    const float* ce = cb + (size_t)t * 64;
#pragma unroll 8
    for (int d = 0; d < 64; d++) {
        float c = ce[d];
        dot = fmaf(s_z[d], c, dot);
        cn = fmaf(c, c, cn);
    }
    s_sc[t] = cn - 2.f * dot;
    __syncthreads();
    if (t == 0) {
        float best = s_sc[0];
        int bi = 0;
        for (int e2 = 1; e2 < 64; e2++)
            if (s_sc[e2] < best) { best = s_sc[e2]; bi = e2; }
        s_best = bi;
    }
    __syncthreads();
    float zq = cb[(size_t)s_best * 64 + t];
    out[(size_t)n * 64 + t] = zq;
    float df = s_z[t] - zq;
    df = df * df;
#pragma unroll
    for (int o = 16; o; o >>= 1) df += __shfl_xor_sync(0xffffffffu, df, o);
    __shared__ float s_part[2];
    if ((t & 31) == 0) s_part[t >> 5] = df;
    __syncthreads();
    if (t == 0) atomicAdd(&g_loss, (double)(s_part[0] + s_part[1]));
}

__global__ void fin_loss_kernel(float* __restrict__ out) {
    out[(size_t)NN * OUTD] = (float)(0.25 * g_loss / (double)((size_t)NN * OUTD));
}

// ---------------- launch ----------------
extern "C" void kernel_launch(void* const* d_in, const int* in_sizes, int n_in,
                              void* d_out, int out_size) {
    const float *x, *coors, *Wq, *Wk, *Wv, *wg, *Wr1, *br1, *Wr2, *br2, *Wo;
    const float *a1, *g1, *b1, *Wlin, *blin, *a2, *g2, *b2, *Wout, *bout, *cb;
    const int* nbr;

    if (n_in > 5 && in_sizes[5] == 2048) {
        // reference-signature order (nbr_idx last)
        x = (const float*)d_in[0];   coors = (const float*)d_in[1];
        Wq = (const float*)d_in[2];  Wk = (const float*)d_in[3];  Wv = (const float*)d_in[4];
        wg = (const float*)d_in[5];  Wr1 = (const float*)d_in[6]; br1 = (const float*)d_in[7];
        Wr2 = (const float*)d_in[8]; br2 = (const float*)d_in[9]; Wo = (const float*)d_in[10];
        a1 = (const float*)d_in[11]; g1 = (const float*)d_in[12]; b1 = (const float*)d_in[13];
        Wlin = (const float*)d_in[14]; blin = (const float*)d_in[15];
        a2 = (const float*)d_in[16]; g2 = (const float*)d_in[17]; b2 = (const float*)d_in[18];
        Wout = (const float*)d_in[19]; bout = (const float*)d_in[20];
        cb = (const float*)d_in[21]; nbr = (const int*)d_in[22];
    } else {
        // setup_inputs dict order
        x = (const float*)d_in[0];   coors = (const float*)d_in[1];
        nbr = (const int*)d_in[2];
        Wq = (const float*)d_in[3];  Wk = (const float*)d_in[4];  Wv = (const float*)d_in[5];
        wg = (const float*)d_in[6];  Wr1 = (const float*)d_in[7]; br1 = (const float*)d_in[8];
        Wr2 = (const float*)d_in[9]; br2 = (const float*)d_in[10]; Wo = (const float*)d_in[11];
        a1 = (const float*)d_in[12]; g1 = (const float*)d_in[13]; b1 = (const float*)d_in[14];
        Wlin = (const float*)d_in[15]; blin = (const float*)d_in[16];
        a2 = (const float*)d_in[17]; g2 = (const float*)d_in[18]; b2 = (const float*)d_in[19];
        Wout = (const float*)d_in[20]; bout = (const float*)d_in[21];
        cb = (const float*)d_in[22];
    }

    float *pQKV, *pAtt, *pT, *pH2, *pZ;
    cudaGetSymbolAddress((void**)&pQKV, g_QKV);
    cudaGetSymbolAddress((void**)&pAtt, g_Att);
    cudaGetSymbolAddress((void**)&pT, g_T);
    cudaGetSymbolAddress((void**)&pH2, g_H2);
    cudaGetSymbolAddress((void**)&pZ, g_Z);

    float* out = (float*)d_out;

    zero_loss_kernel<<<1, 1>>>();

    // fused QKV projection: [x] @ [Wq|Wk|Wv] -> g_QKV
    gemmT<0, 1><<<dim3(QKVW / 128, NN / 128), 256>>>(
        x, Wq, Wk, Wv, pQKV, NN, CC, HD, QKVW,
        nullptr, nullptr, 0, nullptr, nullptr, nullptr);
    gate_kernel<<<(NN * HH + 255) / 256, 256>>>(x, wg);

    attn_kernel<<<NN, 256>>>(coors, nbr, Wr1, br1, Wr2, br2);

    // se3_out = x + Att@Wo, fused DynTanh -> T
    gemmT<1, 0><<<dim3(CC / 128, NN / 128), 256>>>(
        pAtt, Wo, nullptr, nullptr, pT, NN, ATTW, CC, CC,
        nullptr, x, CC, a1, g1, b1);
    // H2[:, :512] = dyntanh2(gelu(T@Wlin + blin))
    gemmT<2, 0><<<dim3(HIDD / 128, NN / 128), 256>>>(
        pT, Wlin, nullptr, nullptr, pH2, NN, CC, HIDD, H2D,
        blin, nullptr, 0, a2, g2, b2);
    h2extra_kernel<<<(NN * 20 + 255) / 256, 256>>>(x, a2, g2, b2);

    // Z = tanh(gelu(H2@Wout + bout))
    gemm64o<<<dim3(OUTD / 64, NN / 64), 256>>>(pH2, Wout, pZ, NN, OUTD, H2D, OUTD, bout);

    vq_kernel<<<NN, 64>>>(cb, out);
    if (out_size > NN * OUTD) fin_loss_kernel<<<1, 1>>>(out);
}